// round 2
// baseline (speedup 1.0000x reference)
#include <cuda_runtime.h>

// MomentumLIF: x[N,T,D] f32 -> spikes[N,T,D] f32
//   v_t = mom*v + x_t - lamb*u
//   u_t = 0.5*u + v_t        (decay = 1 - 1/tau, tau=2)
//   s_t = (u_t >= 1)
//   u_t = u_t * (1 - s_t)
// Each (n,d) lane is an independent serial recurrence over T=64.
// One thread handles 4 consecutive d (float4), keeping u/v in registers.

#define LIF_N 64
#define LIF_T 64
#define LIF_D 8192
#define LIF_D4 (LIF_D / 4)          // 2048 float4 per row
#define THREADS 256

__global__ __launch_bounds__(THREADS)
void momentum_lif_kernel(const float4* __restrict__ x,
                         const float* __restrict__ p_mom,
                         const float* __restrict__ p_lamb,
                         float4* __restrict__ out) {
    const float mom = __ldg(p_mom);
    const float lb  = __ldg(p_lamb);

    int idx = blockIdx.x * THREADS + threadIdx.x;   // 0 .. N*D4-1 (exact grid)
    int n  = idx >> 11;          // idx / 2048
    int d4 = idx & 2047;         // idx % 2048

    const float4* xp = x   + (size_t)n * LIF_T * LIF_D4 + d4;
    float4*       op = out + (size_t)n * LIF_T * LIF_D4 + d4;

    float ux = 0.f, uy = 0.f, uz = 0.f, uw = 0.f;
    float vx = 0.f, vy = 0.f, vz = 0.f, vw = 0.f;

#pragma unroll
    for (int t = 0; t < LIF_T; ++t) {
        float4 xv = xp[(size_t)t * LIF_D4];

        // lane x
        vx = fmaf(mom, vx, xv.x);
        vx = fmaf(-lb, ux, vx);
        ux = fmaf(0.5f, ux, vx);
        float sx = (ux >= 1.0f) ? 1.0f : 0.0f;
        ux = (ux >= 1.0f) ? 0.0f : ux;
        // lane y
        vy = fmaf(mom, vy, xv.y);
        vy = fmaf(-lb, uy, vy);
        uy = fmaf(0.5f, uy, vy);
        float sy = (uy >= 1.0f) ? 1.0f : 0.0f;
        uy = (uy >= 1.0f) ? 0.0f : uy;
        // lane z
        vz = fmaf(mom, vz, xv.z);
        vz = fmaf(-lb, uz, vz);
        uz = fmaf(0.5f, uz, vz);
        float sz = (uz >= 1.0f) ? 1.0f : 0.0f;
        uz = (uz >= 1.0f) ? 0.0f : uz;
        // lane w
        vw = fmaf(mom, vw, xv.w);
        vw = fmaf(-lb, uw, vw);
        uw = fmaf(0.5f, uw, vw);
        float sw = (uw >= 1.0f) ? 1.0f : 0.0f;
        uw = (uw >= 1.0f) ? 0.0f : uw;

        op[(size_t)t * LIF_D4] = make_float4(sx, sy, sz, sw);
    }
}

extern "C" void kernel_launch(void* const* d_in, const int* in_sizes, int n_in,
                              void* d_out, int out_size) {
    const float4* x      = (const float4*)d_in[0];
    const float*  p_mom  = (const float*)d_in[1];
    const float*  p_lamb = (const float*)d_in[2];
    float4*       out    = (float4*)d_out;

    const int total = LIF_N * LIF_D4;           // 131072 threads
    momentum_lif_kernel<<<total / THREADS, THREADS>>>(x, p_mom, p_lamb, out);
}